// round 1
// baseline (speedup 1.0000x reference)
#include <cuda_runtime.h>
#include <math.h>

#define UNITS        128
#define ROWS_PER_CTA 16
#define NCTA         128
#define NTHREADS     256
#define N_ITER       64
#define ZS_STRIDE    20    // 16 rows + 4 pad (keeps 16B alignment, breaks bank patterns)
#define WT_STRIDE    129   // 128 + 1 pad -> conflict-free lane-consecutive reads

// Dynamic shared layout (floats):
//   sWt : 128*129 = 16512   (W transposed; reused for W_in tiles and W_out)
//   sZ  : 128*20  = 2560    (z transposed [unit][row])
//   sXb : 128*20  = 2560    (block input transposed [unit][row])
#define SWT_OFF 0
#define SZ_OFF  16512
#define SXB_OFF (16512 + 2560)
#define SMEM_FLOATS (16512 + 2560 + 2560)
#define SMEM_BYTES  (SMEM_FLOATS * 4)

__device__ __forceinline__ unsigned long long pack2(float lo, float hi) {
    unsigned long long r;
    asm("mov.b64 %0, {%1, %2};" : "=l"(r) : "f"(lo), "f"(hi));
    return r;
}
__device__ __forceinline__ float2 unpack2(unsigned long long v) {
    float2 f;
    asm("mov.b64 {%0, %1}, %2;" : "=f"(f.x), "=f"(f.y) : "l"(v));
    return f;
}
// packed fp32x2 FMA (SASS FFMA2) -- 2x fp32 FMA throughput on sm_103a
__device__ __forceinline__ unsigned long long fma2(unsigned long long a,
                                                   unsigned long long b,
                                                   unsigned long long c) {
    unsigned long long d;
    asm("fma.rn.f32x2 %0, %1, %2, %3;" : "=l"(d) : "l"(a), "l"(b), "l"(c));
    return d;
}

extern __shared__ float smem[];

__global__ __launch_bounds__(NTHREADS, 1)
void newton_net_kernel(const float* __restrict__ x,
                       const float* __restrict__ W_in,
                       const float* __restrict__ b_in,
                       const float* __restrict__ W1,
                       const float* __restrict__ W2,
                       const float* __restrict__ W3,
                       const float* __restrict__ W4,
                       const float* __restrict__ W_out,
                       const float* __restrict__ b_out,
                       float* __restrict__ out)
{
    float* sWt = smem + SWT_OFF;
    float* sZ  = smem + SZ_OFF;
    float* sXb = smem + SXB_OFF;

    const int tid  = threadIdx.x;
    const int u    = tid & 127;   // unit this thread owns
    const int g    = tid >> 7;    // row-half (0 or 1)
    const int roff = g * 8;       // first of 8 rows handled
    const int row0 = blockIdx.x * ROWS_PER_CTA;

    // =========== Phase 0: xb = x @ W_in^T + b_in  (K=784 tiled by 112) ===========
    unsigned long long a0 = 0ull, a1 = 0ull, a2 = 0ull, a3 = 0ull; // bits of (0.f,0.f)
    const int KT = 112;
    for (int kt = 0; kt < 7; ++kt) {
        // load W_in tile transposed: sWt[i*129 + uu] = W_in[uu*784 + kt*112 + i]
        for (int idx = tid; idx < UNITS * KT; idx += NTHREADS) {
            int uu = idx / KT;
            int ii = idx - uu * KT;
            sWt[ii * WT_STRIDE + uu] = W_in[uu * 784 + kt * KT + ii];
        }
        // load x tile transposed: sZ[i*20 + r] = x[(row0+r)*784 + kt*112 + i]
        for (int idx = tid; idx < ROWS_PER_CTA * KT; idx += NTHREADS) {
            int rr = idx / KT;
            int ii = idx - rr * KT;
            sZ[ii * ZS_STRIDE + rr] = x[(row0 + rr) * 784 + kt * KT + ii];
        }
        __syncthreads();
        #pragma unroll 8
        for (int i = 0; i < KT; ++i) {
            float w = sWt[i * WT_STRIDE + u];
            unsigned long long wv = pack2(w, w);
            ulonglong2 zp = *(const ulonglong2*)&sZ[i * ZS_STRIDE + roff];
            ulonglong2 zq = *(const ulonglong2*)&sZ[i * ZS_STRIDE + roff + 4];
            a0 = fma2(zp.x, wv, a0);
            a1 = fma2(zp.y, wv, a1);
            a2 = fma2(zq.x, wv, a2);
            a3 = fma2(zq.y, wv, a3);
        }
        __syncthreads();
    }
    {
        float bv = b_in[u];
        float2 t0 = unpack2(a0), t1 = unpack2(a1), t2 = unpack2(a2), t3 = unpack2(a3);
        float4 v0 = make_float4(t0.x + bv, t0.y + bv, t1.x + bv, t1.y + bv);
        float4 v1 = make_float4(t2.x + bv, t2.y + bv, t3.x + bv, t3.y + bv);
        *(float4*)&sXb[u * ZS_STRIDE + roff]     = v0;
        *(float4*)&sXb[u * ZS_STRIDE + roff + 4] = v1;
    }
    __syncthreads();

    // =========== Phase 1..4: implicit blocks via Picard iteration ===========
    const float* Ws[4] = { W1, W2, W3, W4 };
    for (int blk = 0; blk < 4; ++blk) {
        const float* Wb = Ws[blk];
        // load W transposed: sWt[k*129 + uu] = Wb[uu*128 + k]  (coalesced reads)
        for (int idx = tid; idx < UNITS * UNITS; idx += NTHREADS) {
            int uu = idx >> 7;
            int kk = idx & 127;
            sWt[kk * WT_STRIDE + uu] = Wb[idx];
        }
        // z0 = tanh(xb)
        {
            float4 v0 = *(const float4*)&sXb[u * ZS_STRIDE + roff];
            float4 v1 = *(const float4*)&sXb[u * ZS_STRIDE + roff + 4];
            v0 = make_float4(tanhf(v0.x), tanhf(v0.y), tanhf(v0.z), tanhf(v0.w));
            v1 = make_float4(tanhf(v1.x), tanhf(v1.y), tanhf(v1.z), tanhf(v1.w));
            *(float4*)&sZ[u * ZS_STRIDE + roff]     = v0;
            *(float4*)&sZ[u * ZS_STRIDE + roff + 4] = v1;
        }
        __syncthreads();

        for (int it = 0; it < N_ITER; ++it) {
            unsigned long long c0, c1, c2, c3;
            {
                float4 xv0 = *(const float4*)&sXb[u * ZS_STRIDE + roff];
                float4 xv1 = *(const float4*)&sXb[u * ZS_STRIDE + roff + 4];
                c0 = pack2(xv0.x, xv0.y);
                c1 = pack2(xv0.z, xv0.w);
                c2 = pack2(xv1.x, xv1.y);
                c3 = pack2(xv1.z, xv1.w);
            }
            #pragma unroll 16
            for (int k = 0; k < UNITS; ++k) {
                float w = sWt[k * WT_STRIDE + u];
                unsigned long long wv = pack2(w, w);
                ulonglong2 zp = *(const ulonglong2*)&sZ[k * ZS_STRIDE + roff];
                ulonglong2 zq = *(const ulonglong2*)&sZ[k * ZS_STRIDE + roff + 4];
                c0 = fma2(zp.x, wv, c0);
                c1 = fma2(zp.y, wv, c1);
                c2 = fma2(zq.x, wv, c2);
                c3 = fma2(zq.y, wv, c3);
            }
            float2 t0 = unpack2(c0), t1 = unpack2(c1), t2 = unpack2(c2), t3 = unpack2(c3);
            float4 o0 = make_float4(tanhf(t0.x), tanhf(t0.y), tanhf(t1.x), tanhf(t1.y));
            float4 o1 = make_float4(tanhf(t2.x), tanhf(t2.y), tanhf(t3.x), tanhf(t3.y));
            __syncthreads();  // all reads of sZ complete
            *(float4*)&sZ[u * ZS_STRIDE + roff]     = o0;
            *(float4*)&sZ[u * ZS_STRIDE + roff + 4] = o1;
            __syncthreads();  // new z visible
        }

        // block output becomes next block input
        {
            float4 v0 = *(const float4*)&sZ[u * ZS_STRIDE + roff];
            float4 v1 = *(const float4*)&sZ[u * ZS_STRIDE + roff + 4];
            *(float4*)&sXb[u * ZS_STRIDE + roff]     = v0;
            *(float4*)&sXb[u * ZS_STRIDE + roff + 4] = v1;
        }
        __syncthreads();
    }

    // =========== Phase 5: logits = z @ W_out^T + b_out, softmax ===========
    for (int idx = tid; idx < 10 * UNITS; idx += NTHREADS) sWt[idx] = W_out[idx];
    if (tid < 10) sWt[1280 + tid] = b_out[tid];
    __syncthreads();
    float* slog = sWt + 1312;
    if (tid < ROWS_PER_CTA * 10) {
        int r = tid / 10;
        int o = tid - r * 10;
        float acc = sWt[1280 + o];
        #pragma unroll 8
        for (int k = 0; k < UNITS; ++k)
            acc += sZ[k * ZS_STRIDE + r] * sWt[o * UNITS + k];
        slog[r * 10 + o] = acc;
    }
    __syncthreads();
    if (tid < ROWS_PER_CTA) {
        int r = tid;
        float l[10];
        float m = -INFINITY;
        #pragma unroll
        for (int o = 0; o < 10; ++o) { l[o] = slog[r * 10 + o]; m = fmaxf(m, l[o]); }
        float s = 0.f;
        #pragma unroll
        for (int o = 0; o < 10; ++o) { l[o] = expf(l[o] - m); s += l[o]; }
        float inv = 1.f / s;
        #pragma unroll
        for (int o = 0; o < 10; ++o) out[(row0 + r) * 10 + o] = l[o] * inv;
    }
}

extern "C" void kernel_launch(void* const* d_in, const int* in_sizes, int n_in,
                              void* d_out, int out_size)
{
    const float* x     = (const float*)d_in[0];
    const float* W_in  = (const float*)d_in[1];
    const float* b_in  = (const float*)d_in[2];
    const float* W1    = (const float*)d_in[3];
    const float* W2    = (const float*)d_in[4];
    const float* W3    = (const float*)d_in[5];
    const float* W4    = (const float*)d_in[6];
    const float* W_out = (const float*)d_in[7];
    const float* b_out = (const float*)d_in[8];
    float* out = (float*)d_out;

    cudaFuncSetAttribute(newton_net_kernel,
                         cudaFuncAttributeMaxDynamicSharedMemorySize, SMEM_BYTES);

    newton_net_kernel<<<NCTA, NTHREADS, SMEM_BYTES>>>(
        x, W_in, b_in, W1, W2, W3, W4, W_out, b_out, out);
}

// round 2
// speedup vs baseline: 2.2757x; 2.2757x over previous
#include <cuda_runtime.h>
#include <math.h>

#define UNITS        128
#define ROWS_PER_CTA 16
#define NCTA         128
#define NTHREADS     128
#define N_ITER       36
#define ZS           20    // z buffer stride (floats): 16 rows + 4 pad, 16B aligned
#define WS           130   // W^T stride (floats): 128 + 2 pad, 8B aligned rows

// shared layout (floats)
#define SWT_OFF 0
#define SZA_OFF 16640
#define SZB_OFF (16640 + 2560)
#define SXB_OFF (16640 + 5120)
#define SMEM_FLOATS (16640 + 7680)
#define SMEM_BYTES  (SMEM_FLOATS * 4)

__device__ __forceinline__ unsigned long long pack2(float lo, float hi) {
    unsigned long long r;
    asm("mov.b64 %0, {%1, %2};" : "=l"(r) : "f"(lo), "f"(hi));
    return r;
}
__device__ __forceinline__ float2 unpack2(unsigned long long v) {
    float2 f;
    asm("mov.b64 {%0, %1}, %2;" : "=f"(f.x), "=f"(f.y) : "l"(v));
    return f;
}
// packed fp32x2 FMA (SASS FFMA2): 2x fp32 FMA throughput
__device__ __forceinline__ unsigned long long fma2(unsigned long long a,
                                                   unsigned long long b,
                                                   unsigned long long c) {
    unsigned long long d;
    asm("fma.rn.f32x2 %0, %1, %2, %3;" : "=l"(d) : "l"(a), "l"(b), "l"(c));
    return d;
}
// fast tanh: 1 - 2/(exp(2x)+1) via MUFU ex2 + rcp (rel err ~1e-6)
__device__ __forceinline__ float fast_tanh(float x) {
    float e, r;
    asm("ex2.approx.f32 %0, %1;" : "=f"(e) : "f"(x * 2.8853900817779268f)); // 2*log2(e)
    asm("rcp.approx.f32 %0, %1;" : "=f"(r) : "f"(e + 1.0f));
    return fmaf(-2.0f, r, 1.0f);
}

extern __shared__ float smem[];

__global__ __launch_bounds__(NTHREADS, 1)
void newton_net_kernel(const float* __restrict__ x,
                       const float* __restrict__ W_in,
                       const float* __restrict__ b_in,
                       const float* __restrict__ W1,
                       const float* __restrict__ W2,
                       const float* __restrict__ W3,
                       const float* __restrict__ W4,
                       const float* __restrict__ W_out,
                       const float* __restrict__ b_out,
                       float* __restrict__ out)
{
    float* sWt = smem + SWT_OFF;

    const int tid  = threadIdx.x;
    const int u2   = tid & 63;         // unit pair: owns units 2*u2, 2*u2+1
    const int g    = tid >> 6;         // row group (0 or 1)
    const int roff = g * 8;            // first of 8 rows
    const int row0 = blockIdx.x * ROWS_PER_CTA;
    const int ub   = 2 * u2;           // base unit

    float* bufX = smem + SXB_OFF;
    float* buf1 = smem + SZA_OFF;
    float* buf2 = smem + SZB_OFF;

    // =========== Phase 0: xb = x @ W_in^T + b_in (K=784, tiled by 112) ===========
    {
        unsigned long long a0[4] = {0ull,0ull,0ull,0ull};
        unsigned long long a1[4] = {0ull,0ull,0ull,0ull};
        for (int kt = 0; kt < 7; ++kt) {
            // W_in tile transposed: sWt[k*WS + u] = W_in[u*784 + kt*112 + k]
            for (int idx = tid; idx < 128 * 28; idx += NTHREADS) {
                int uu = idx / 28;
                int i4 = idx - uu * 28;
                float4 v = *(const float4*)(W_in + uu * 784 + kt * 112 + i4 * 4);
                int kb = i4 * 4;
                sWt[(kb + 0) * WS + uu] = v.x;
                sWt[(kb + 1) * WS + uu] = v.y;
                sWt[(kb + 2) * WS + uu] = v.z;
                sWt[(kb + 3) * WS + uu] = v.w;
            }
            // x tile transposed: buf1[k*ZS + r]
            for (int idx = tid; idx < 16 * 28; idx += NTHREADS) {
                int rr = idx / 28;
                int i4 = idx - rr * 28;
                float4 v = *(const float4*)(x + (row0 + rr) * 784 + kt * 112 + i4 * 4);
                int kb = i4 * 4;
                buf1[(kb + 0) * ZS + rr] = v.x;
                buf1[(kb + 1) * ZS + rr] = v.y;
                buf1[(kb + 2) * ZS + rr] = v.z;
                buf1[(kb + 3) * ZS + rr] = v.w;
            }
            __syncthreads();
            #pragma unroll 8
            for (int k = 0; k < 112; ++k) {
                float2 w = *(const float2*)&sWt[k * WS + ub];
                unsigned long long wx = pack2(w.x, w.x);
                unsigned long long wy = pack2(w.y, w.y);
                ulonglong2 zp = *(const ulonglong2*)&buf1[k * ZS + roff];
                ulonglong2 zq = *(const ulonglong2*)&buf1[k * ZS + roff + 4];
                a0[0] = fma2(zp.x, wx, a0[0]);  a0[1] = fma2(zp.y, wx, a0[1]);
                a0[2] = fma2(zq.x, wx, a0[2]);  a0[3] = fma2(zq.y, wx, a0[3]);
                a1[0] = fma2(zp.x, wy, a1[0]);  a1[1] = fma2(zp.y, wy, a1[1]);
                a1[2] = fma2(zq.x, wy, a1[2]);  a1[3] = fma2(zq.y, wy, a1[3]);
            }
            __syncthreads();
        }
        float bv0 = b_in[ub], bv1 = b_in[ub + 1];
        #pragma unroll
        for (int j = 0; j < 2; ++j) {
            unsigned long long* a = j ? a1 : a0;
            float bv = j ? bv1 : bv0;
            float2 t0 = unpack2(a[0]), t1 = unpack2(a[1]);
            float2 t2 = unpack2(a[2]), t3 = unpack2(a[3]);
            *(float4*)&bufX[(ub + j) * ZS + roff] =
                make_float4(t0.x + bv, t0.y + bv, t1.x + bv, t1.y + bv);
            *(float4*)&bufX[(ub + j) * ZS + roff + 4] =
                make_float4(t2.x + bv, t2.y + bv, t3.x + bv, t3.y + bv);
        }
        __syncthreads();
    }

    // =========== Phases 1..4: implicit blocks (Picard, ping-pong z) ===========
    const float* Ws[4] = { W1, W2, W3, W4 };
    for (int blk = 0; blk < 4; ++blk) {
        const float* Wb = Ws[blk];
        // load W transposed: sWt[k*WS + u] = Wb[u*128 + k]
        for (int idx = tid; idx < UNITS * UNITS / 4; idx += NTHREADS) {
            int uu = idx >> 5;
            int k4 = idx & 31;
            float4 v = *(const float4*)(Wb + uu * 128 + k4 * 4);
            int kb = 4 * k4;
            sWt[(kb + 0) * WS + uu] = v.x;
            sWt[(kb + 1) * WS + uu] = v.y;
            sWt[(kb + 2) * WS + uu] = v.z;
            sWt[(kb + 3) * WS + uu] = v.w;
        }
        // z0 = tanh(xb) -> buf1
        for (int idx = tid; idx < UNITS * ROWS_PER_CTA; idx += NTHREADS) {
            int uu = idx >> 4;
            int rr = idx & 15;
            buf1[uu * ZS + rr] = fast_tanh(bufX[uu * ZS + rr]);
        }
        __syncthreads();

        float* cur = buf1;
        float* nxt = buf2;
        for (int it = 0; it < N_ITER; ++it) {
            unsigned long long c0[4], c1[4];
            {
                float4 x0 = *(const float4*)&bufX[(ub) * ZS + roff];
                float4 x1 = *(const float4*)&bufX[(ub) * ZS + roff + 4];
                float4 y0 = *(const float4*)&bufX[(ub + 1) * ZS + roff];
                float4 y1 = *(const float4*)&bufX[(ub + 1) * ZS + roff + 4];
                c0[0] = pack2(x0.x, x0.y);  c0[1] = pack2(x0.z, x0.w);
                c0[2] = pack2(x1.x, x1.y);  c0[3] = pack2(x1.z, x1.w);
                c1[0] = pack2(y0.x, y0.y);  c1[1] = pack2(y0.z, y0.w);
                c1[2] = pack2(y1.x, y1.y);  c1[3] = pack2(y1.z, y1.w);
            }
            #pragma unroll 16
            for (int k = 0; k < UNITS; ++k) {
                float2 w = *(const float2*)&sWt[k * WS + ub];
                unsigned long long wx = pack2(w.x, w.x);
                unsigned long long wy = pack2(w.y, w.y);
                ulonglong2 zp = *(const ulonglong2*)&cur[k * ZS + roff];
                ulonglong2 zq = *(const ulonglong2*)&cur[k * ZS + roff + 4];
                c0[0] = fma2(zp.x, wx, c0[0]);  c0[1] = fma2(zp.y, wx, c0[1]);
                c0[2] = fma2(zq.x, wx, c0[2]);  c0[3] = fma2(zq.y, wx, c0[3]);
                c1[0] = fma2(zp.x, wy, c1[0]);  c1[1] = fma2(zp.y, wy, c1[1]);
                c1[2] = fma2(zq.x, wy, c1[2]);  c1[3] = fma2(zq.y, wy, c1[3]);
            }
            #pragma unroll
            for (int j = 0; j < 2; ++j) {
                unsigned long long* c = j ? c1 : c0;
                float2 t0 = unpack2(c[0]), t1 = unpack2(c[1]);
                float2 t2 = unpack2(c[2]), t3 = unpack2(c[3]);
                float4 o0 = make_float4(fast_tanh(t0.x), fast_tanh(t0.y),
                                        fast_tanh(t1.x), fast_tanh(t1.y));
                float4 o1 = make_float4(fast_tanh(t2.x), fast_tanh(t2.y),
                                        fast_tanh(t3.x), fast_tanh(t3.y));
                *(float4*)&nxt[(ub + j) * ZS + roff]     = o0;
                *(float4*)&nxt[(ub + j) * ZS + roff + 4] = o1;
            }
            __syncthreads();
            float* t = cur; cur = nxt; nxt = t;
        }

        // rotate buffers: block output (cur) becomes next block input
        float* oldX = bufX;
        bufX = cur;
        buf1 = oldX;
        buf2 = nxt;
        __syncthreads();
    }

    // =========== Phase 5: logits + softmax ===========
    for (int idx = tid; idx < 10 * UNITS; idx += NTHREADS) sWt[idx] = W_out[idx];
    if (tid < 10) sWt[1280 + tid] = b_out[tid];
    __syncthreads();
    float* slog = sWt + 1296;   // [o][r] layout, 160 floats
    for (int idx = tid; idx < 160; idx += NTHREADS) {
        int o = idx >> 4;
        int r = idx & 15;
        float acc = sWt[1280 + o];
        #pragma unroll 8
        for (int k = 0; k < UNITS; ++k)
            acc += bufX[k * ZS + r] * sWt[o * UNITS + k];
        slog[o * 16 + r] = acc;
    }
    __syncthreads();
    if (tid < ROWS_PER_CTA) {
        int r = tid;
        float l[10];
        float m = -INFINITY;
        #pragma unroll
        for (int o = 0; o < 10; ++o) { l[o] = slog[o * 16 + r]; m = fmaxf(m, l[o]); }
        float s = 0.f;
        #pragma unroll
        for (int o = 0; o < 10; ++o) { l[o] = expf(l[o] - m); s += l[o]; }
        float inv = 1.f / s;
        #pragma unroll
        for (int o = 0; o < 10; ++o) out[(row0 + r) * 10 + o] = l[o] * inv;
    }
}

extern "C" void kernel_launch(void* const* d_in, const int* in_sizes, int n_in,
                              void* d_out, int out_size)
{
    const float* x     = (const float*)d_in[0];
    const float* W_in  = (const float*)d_in[1];
    const float* b_in  = (const float*)d_in[2];
    const float* W1    = (const float*)d_in[3];
    const float* W2    = (const float*)d_in[4];
    const float* W3    = (const float*)d_in[5];
    const float* W4    = (const float*)d_in[6];
    const float* W_out = (const float*)d_in[7];
    const float* b_out = (const float*)d_in[8];
    float* out = (float*)d_out;

    cudaFuncSetAttribute(newton_net_kernel,
                         cudaFuncAttributeMaxDynamicSharedMemorySize, SMEM_BYTES);

    newton_net_kernel<<<NCTA, NTHREADS, SMEM_BYTES>>>(
        x, W_in, b_in, W1, W2, W3, W4, W_out, b_out, out);
}

// round 3
// speedup vs baseline: 3.8724x; 1.7016x over previous
#include <cuda_runtime.h>
#include <math.h>

#define UNITS        128
#define ROWS_PER_CTA 16
#define NCTA         128
#define NTHREADS     128
#define N_ITER       20
#define ZS           20    // z buffer stride (floats): 16 rows + 4 pad, 16B aligned
#define WS           130   // W^T stride (floats): 128 + 2 pad, 8B aligned rows

// shared layout (floats)
#define SWT_OFF 0
#define SZA_OFF 16640
#define SZB_OFF (16640 + 2560)
#define SXB_OFF (16640 + 5120)
#define SMEM_FLOATS (16640 + 7680)
#define SMEM_BYTES  (SMEM_FLOATS * 4)

__device__ __forceinline__ unsigned long long pack2(float lo, float hi) {
    unsigned long long r;
    asm("mov.b64 %0, {%1, %2};" : "=l"(r) : "f"(lo), "f"(hi));
    return r;
}
__device__ __forceinline__ float2 unpack2(unsigned long long v) {
    float2 f;
    asm("mov.b64 {%0, %1}, %2;" : "=f"(f.x), "=f"(f.y) : "l"(v));
    return f;
}
// packed fp32x2 FMA (SASS FFMA2): 2x fp32 FMA throughput
__device__ __forceinline__ unsigned long long fma2(unsigned long long a,
                                                   unsigned long long b,
                                                   unsigned long long c) {
    unsigned long long d;
    asm("fma.rn.f32x2 %0, %1, %2, %3;" : "=l"(d) : "l"(a), "l"(b), "l"(c));
    return d;
}
// fast tanh: 1 - 2/(exp(2x)+1) via MUFU ex2 + rcp (rel err ~1e-6)
__device__ __forceinline__ float fast_tanh(float x) {
    float e, r;
    asm("ex2.approx.f32 %0, %1;" : "=f"(e) : "f"(x * 2.8853900817779268f)); // 2*log2(e)
    asm("rcp.approx.f32 %0, %1;" : "=f"(r) : "f"(e + 1.0f));
    return fmaf(-2.0f, r, 1.0f);
}

extern __shared__ float smem[];

__global__ __launch_bounds__(NTHREADS, 1)
void newton_net_kernel(const float* __restrict__ x,
                       const float* __restrict__ W_in,
                       const float* __restrict__ b_in,
                       const float* __restrict__ W1,
                       const float* __restrict__ W2,
                       const float* __restrict__ W3,
                       const float* __restrict__ W4,
                       const float* __restrict__ W_out,
                       const float* __restrict__ b_out,
                       float* __restrict__ out)
{
    float* sWt = smem + SWT_OFF;

    const int tid  = threadIdx.x;
    const int u2   = tid & 63;         // unit pair: owns units 2*u2, 2*u2+1
    const int g    = tid >> 6;         // row group (0 or 1)
    const int roff = g * 8;            // first of 8 rows
    const int row0 = blockIdx.x * ROWS_PER_CTA;
    const int ub   = 2 * u2;           // base unit

    float* bufX = smem + SXB_OFF;
    float* buf1 = smem + SZA_OFF;
    float* buf2 = smem + SZB_OFF;

    // =========== Phase 0: xb = x @ W_in^T + b_in (K=784, tiled by 112) ===========
    {
        unsigned long long a0[4] = {0ull,0ull,0ull,0ull};
        unsigned long long a1[4] = {0ull,0ull,0ull,0ull};
        for (int kt = 0; kt < 7; ++kt) {
            // W_in tile transposed: sWt[k*WS + u] = W_in[u*784 + kt*112 + k]
            for (int idx = tid; idx < 128 * 28; idx += NTHREADS) {
                int uu = idx / 28;
                int i4 = idx - uu * 28;
                float4 v = *(const float4*)(W_in + uu * 784 + kt * 112 + i4 * 4);
                int kb = i4 * 4;
                sWt[(kb + 0) * WS + uu] = v.x;
                sWt[(kb + 1) * WS + uu] = v.y;
                sWt[(kb + 2) * WS + uu] = v.z;
                sWt[(kb + 3) * WS + uu] = v.w;
            }
            // x tile transposed: buf1[k*ZS + r]
            for (int idx = tid; idx < 16 * 28; idx += NTHREADS) {
                int rr = idx / 28;
                int i4 = idx - rr * 28;
                float4 v = *(const float4*)(x + (row0 + rr) * 784 + kt * 112 + i4 * 4);
                int kb = i4 * 4;
                buf1[(kb + 0) * ZS + rr] = v.x;
                buf1[(kb + 1) * ZS + rr] = v.y;
                buf1[(kb + 2) * ZS + rr] = v.z;
                buf1[(kb + 3) * ZS + rr] = v.w;
            }
            __syncthreads();
            #pragma unroll 14
            for (int k = 0; k < 112; ++k) {
                float2 w = *(const float2*)&sWt[k * WS + ub];
                unsigned long long wx = pack2(w.x, w.x);
                unsigned long long wy = pack2(w.y, w.y);
                ulonglong2 zp = *(const ulonglong2*)&buf1[k * ZS + roff];
                ulonglong2 zq = *(const ulonglong2*)&buf1[k * ZS + roff + 4];
                a0[0] = fma2(zp.x, wx, a0[0]);  a0[1] = fma2(zp.y, wx, a0[1]);
                a0[2] = fma2(zq.x, wx, a0[2]);  a0[3] = fma2(zq.y, wx, a0[3]);
                a1[0] = fma2(zp.x, wy, a1[0]);  a1[1] = fma2(zp.y, wy, a1[1]);
                a1[2] = fma2(zq.x, wy, a1[2]);  a1[3] = fma2(zq.y, wy, a1[3]);
            }
            __syncthreads();
        }
        float bv0 = b_in[ub], bv1 = b_in[ub + 1];
        #pragma unroll
        for (int j = 0; j < 2; ++j) {
            unsigned long long* a = j ? a1 : a0;
            float bv = j ? bv1 : bv0;
            float2 t0 = unpack2(a[0]), t1 = unpack2(a[1]);
            float2 t2 = unpack2(a[2]), t3 = unpack2(a[3]);
            *(float4*)&bufX[(ub + j) * ZS + roff] =
                make_float4(t0.x + bv, t0.y + bv, t1.x + bv, t1.y + bv);
            *(float4*)&bufX[(ub + j) * ZS + roff + 4] =
                make_float4(t2.x + bv, t2.y + bv, t3.x + bv, t3.y + bv);
        }
        __syncthreads();
    }

    // =========== Phases 1..4: implicit blocks (Picard, ping-pong z) ===========
    const float* Ws[4] = { W1, W2, W3, W4 };
    for (int blk = 0; blk < 4; ++blk) {
        const float* Wb = Ws[blk];
        // load W transposed: sWt[k*WS + u] = Wb[u*128 + k]
        for (int idx = tid; idx < UNITS * UNITS / 4; idx += NTHREADS) {
            int uu = idx >> 5;
            int k4 = idx & 31;
            float4 v = *(const float4*)(Wb + uu * 128 + k4 * 4);
            int kb = 4 * k4;
            sWt[(kb + 0) * WS + uu] = v.x;
            sWt[(kb + 1) * WS + uu] = v.y;
            sWt[(kb + 2) * WS + uu] = v.z;
            sWt[(kb + 3) * WS + uu] = v.w;
        }
        // z0 = tanh(xb) -> buf1
        for (int idx = tid; idx < UNITS * ROWS_PER_CTA; idx += NTHREADS) {
            int uu = idx >> 4;
            int rr = idx & 15;
            buf1[uu * ZS + rr] = fast_tanh(bufX[uu * ZS + rr]);
        }
        // hoist this thread's x into registers for the whole iteration loop
        unsigned long long xr[8];
        {
            float4 x0 = *(const float4*)&bufX[(ub) * ZS + roff];
            float4 x1 = *(const float4*)&bufX[(ub) * ZS + roff + 4];
            float4 y0 = *(const float4*)&bufX[(ub + 1) * ZS + roff];
            float4 y1 = *(const float4*)&bufX[(ub + 1) * ZS + roff + 4];
            xr[0] = pack2(x0.x, x0.y);  xr[1] = pack2(x0.z, x0.w);
            xr[2] = pack2(x1.x, x1.y);  xr[3] = pack2(x1.z, x1.w);
            xr[4] = pack2(y0.x, y0.y);  xr[5] = pack2(y0.z, y0.w);
            xr[6] = pack2(y1.x, y1.y);  xr[7] = pack2(y1.z, y1.w);
        }
        __syncthreads();

        float* cur = buf1;
        float* nxt = buf2;
        for (int it = 0; it < N_ITER; ++it) {
            unsigned long long c0[4], c1[4];
            c0[0] = xr[0];  c0[1] = xr[1];  c0[2] = xr[2];  c0[3] = xr[3];
            c1[0] = xr[4];  c1[1] = xr[5];  c1[2] = xr[6];  c1[3] = xr[7];
            #pragma unroll
            for (int k = 0; k < UNITS; ++k) {
                float2 w = *(const float2*)&sWt[k * WS + ub];
                unsigned long long wx = pack2(w.x, w.x);
                unsigned long long wy = pack2(w.y, w.y);
                ulonglong2 zp = *(const ulonglong2*)&cur[k * ZS + roff];
                ulonglong2 zq = *(const ulonglong2*)&cur[k * ZS + roff + 4];
                c0[0] = fma2(zp.x, wx, c0[0]);  c0[1] = fma2(zp.y, wx, c0[1]);
                c0[2] = fma2(zq.x, wx, c0[2]);  c0[3] = fma2(zq.y, wx, c0[3]);
                c1[0] = fma2(zp.x, wy, c1[0]);  c1[1] = fma2(zp.y, wy, c1[1]);
                c1[2] = fma2(zq.x, wy, c1[2]);  c1[3] = fma2(zq.y, wy, c1[3]);
            }
            #pragma unroll
            for (int j = 0; j < 2; ++j) {
                unsigned long long* c = j ? c1 : c0;
                float2 t0 = unpack2(c[0]), t1 = unpack2(c[1]);
                float2 t2 = unpack2(c[2]), t3 = unpack2(c[3]);
                float4 o0 = make_float4(fast_tanh(t0.x), fast_tanh(t0.y),
                                        fast_tanh(t1.x), fast_tanh(t1.y));
                float4 o1 = make_float4(fast_tanh(t2.x), fast_tanh(t2.y),
                                        fast_tanh(t3.x), fast_tanh(t3.y));
                *(float4*)&nxt[(ub + j) * ZS + roff]     = o0;
                *(float4*)&nxt[(ub + j) * ZS + roff + 4] = o1;
            }
            __syncthreads();
            float* t = cur; cur = nxt; nxt = t;
        }

        // rotate buffers: block output (cur) becomes next block input
        float* oldX = bufX;
        bufX = cur;
        buf1 = oldX;
        buf2 = nxt;
        __syncthreads();
    }

    // =========== Phase 5: logits + softmax ===========
    for (int idx = tid; idx < 10 * UNITS; idx += NTHREADS) sWt[idx] = W_out[idx];
    if (tid < 10) sWt[1280 + tid] = b_out[tid];
    __syncthreads();
    float* slog = sWt + 1296;   // [o][r] layout, 160 floats
    for (int idx = tid; idx < 160; idx += NTHREADS) {
        int o = idx >> 4;
        int r = idx & 15;
        float acc = sWt[1280 + o];
        #pragma unroll 8
        for (int k = 0; k < UNITS; ++k)
            acc += bufX[k * ZS + r] * sWt[o * UNITS + k];
        slog[o * 16 + r] = acc;
    }
    __syncthreads();
    if (tid < ROWS_PER_CTA) {
        int r = tid;
        float l[10];
        float m = -INFINITY;
        #pragma unroll
        for (int o = 0; o < 10; ++o) { l[o] = slog[o * 16 + r]; m = fmaxf(m, l[o]); }
        float s = 0.f;
        #pragma unroll
        for (int o = 0; o < 10; ++o) { l[o] = expf(l[o] - m); s += l[o]; }
        float inv = 1.f / s;
        #pragma unroll
        for (int o = 0; o < 10; ++o) out[(row0 + r) * 10 + o] = l[o] * inv;
    }
}

extern "C" void kernel_launch(void* const* d_in, const int* in_sizes, int n_in,
                              void* d_out, int out_size)
{
    const float* x     = (const float*)d_in[0];
    const float* W_in  = (const float*)d_in[1];
    const float* b_in  = (const float*)d_in[2];
    const float* W1    = (const float*)d_in[3];
    const float* W2    = (const float*)d_in[4];
    const float* W3    = (const float*)d_in[5];
    const float* W4    = (const float*)d_in[6];
    const float* W_out = (const float*)d_in[7];
    const float* b_out = (const float*)d_in[8];
    float* out = (float*)d_out;

    cudaFuncSetAttribute(newton_net_kernel,
                         cudaFuncAttributeMaxDynamicSharedMemorySize, SMEM_BYTES);

    newton_net_kernel<<<NCTA, NTHREADS, SMEM_BYTES>>>(
        x, W_in, b_in, W1, W2, W3, W4, W_out, b_out, out);
}

// round 5
// speedup vs baseline: 7.0911x; 1.8312x over previous
#include <cuda_runtime.h>
#include <math.h>
#include <stdint.h>

#define UNITS        128
#define ROWS_PER_CTA 16
#define NCTA         128
#define NTHREADS     128
#define N_ITER       20
#define ZS           20    // bufX stride (floats)
#define WS           130   // phase0 W^T stride (floats)

// ---- shared memory byte layout ----
#define SWT_BYTE   0        // phase0 W tiles / epilogue W_out: 66560 B
#define BUF1_BYTE  66560    // phase0 x tiles: 8960 B
#define BUFX_BYTE  75520    // fp32 x / final z, [u][r] stride ZS: 10240 B
#define ZBH_BYTE   85760    // Z hi bf16 fragments: 4096 B
#define ZBL_BYTE   89856    // Z lo bf16 fragments: 4096 B
#define WLS_BYTE   93952    // Wl fragments (warp-private): 32768 B
#define SMEM_BYTES 126720

__device__ __forceinline__ uint32_t smem_u32(const void* p) {
    uint32_t a;
    asm("{ .reg .u64 t; cvta.to.shared.u64 t, %1; cvt.u32.u64 %0, t; }" : "=r"(a) : "l"(p));
    return a;
}
__device__ __forceinline__ unsigned long long pack2(float lo, float hi) {
    unsigned long long r;
    asm("mov.b64 %0, {%1, %2};" : "=l"(r) : "f"(lo), "f"(hi));
    return r;
}
__device__ __forceinline__ float2 unpack2(unsigned long long v) {
    float2 f;
    asm("mov.b64 {%0, %1}, %2;" : "=f"(f.x), "=f"(f.y) : "l"(v));
    return f;
}
__device__ __forceinline__ unsigned long long fma2(unsigned long long a,
                                                   unsigned long long b,
                                                   unsigned long long c) {
    unsigned long long d;
    asm("fma.rn.f32x2 %0, %1, %2, %3;" : "=l"(d) : "l"(a), "l"(b), "l"(c));
    return d;
}
__device__ __forceinline__ float fast_tanh(float x) {
    float e, r;
    asm("ex2.approx.f32 %0, %1;" : "=f"(e) : "f"(x * 2.8853900817779268f));
    asm("rcp.approx.f32 %0, %1;" : "=f"(r) : "f"(e + 1.0f));
    return fmaf(-2.0f, r, 1.0f);
}
// pack two f32 -> bf16x2 word {hi16=second arg? no: returns (hi<<16)|lo with lo=first}
__device__ __forceinline__ uint32_t bfpack(float lo, float hi) {
    uint32_t r;
    asm("cvt.rn.bf16x2.f32 %0, %1, %2;" : "=r"(r) : "f"(hi), "f"(lo));
    return r;
}
__device__ __forceinline__ unsigned short f2bf(float f) {
    unsigned short h;
    asm("cvt.rn.bf16.f32 %0, %1;" : "=h"(h) : "f"(f));
    return h;
}
// m16n8k16 row.col f32.bf16.bf16.f32
__device__ __forceinline__ void mma_bf16(float* c,
                                         uint32_t a0, uint32_t a1, uint32_t a2, uint32_t a3,
                                         uint32_t b0, uint32_t b1) {
    asm volatile(
        "mma.sync.aligned.m16n8k16.row.col.f32.bf16.bf16.f32 "
        "{%0,%1,%2,%3}, {%4,%5,%6,%7}, {%8,%9}, {%0,%1,%2,%3};"
        : "+f"(c[0]), "+f"(c[1]), "+f"(c[2]), "+f"(c[3])
        : "r"(a0), "r"(a1), "r"(a2), "r"(a3), "r"(b0), "r"(b1));
}

extern __shared__ float smem[];

__global__ __launch_bounds__(NTHREADS, 1)
void newton_net_kernel(const float* __restrict__ x,
                       const float* __restrict__ W_in,
                       const float* __restrict__ b_in,
                       const float* __restrict__ W1,
                       const float* __restrict__ W2,
                       const float* __restrict__ W3,
                       const float* __restrict__ W4,
                       const float* __restrict__ W_out,
                       const float* __restrict__ b_out,
                       float* __restrict__ out)
{
    const int tid  = threadIdx.x;
    const int row0 = blockIdx.x * ROWS_PER_CTA;

    char* smem_c = (char*)smem;
    const uint32_t sbase = smem_u32(smem);
    const uint32_t sZBh  = sbase + ZBH_BYTE;
    const uint32_t sZBl  = sbase + ZBL_BYTE;
    const uint32_t sWls  = sbase + WLS_BYTE;

    float* sWt  = smem;                           // phase0 / epilogue
    float* buf1 = (float*)(smem_c + BUF1_BYTE);   // phase0 x tiles
    float* bufX = (float*)(smem_c + BUFX_BYTE);   // [u*ZS + r] fp32

    // =========== Phase 0: xb = x @ W_in^T + b_in (FFMA2, K=784 in 7 tiles) ===========
    {
        const int u2   = tid & 63;
        const int gg   = tid >> 6;
        const int roff = gg * 8;
        const int ub   = 2 * u2;
        unsigned long long a0[4] = {0ull,0ull,0ull,0ull};
        unsigned long long a1[4] = {0ull,0ull,0ull,0ull};
        for (int kt = 0; kt < 7; ++kt) {
            for (int idx = tid; idx < 128 * 28; idx += NTHREADS) {
                int uu = idx / 28;
                int i4 = idx - uu * 28;
                float4 v = *(const float4*)(W_in + uu * 784 + kt * 112 + i4 * 4);
                int kb = i4 * 4;
                sWt[(kb + 0) * WS + uu] = v.x;
                sWt[(kb + 1) * WS + uu] = v.y;
                sWt[(kb + 2) * WS + uu] = v.z;
                sWt[(kb + 3) * WS + uu] = v.w;
            }
            for (int idx = tid; idx < 16 * 28; idx += NTHREADS) {
                int rr = idx / 28;
                int i4 = idx - rr * 28;
                float4 v = *(const float4*)(x + (row0 + rr) * 784 + kt * 112 + i4 * 4);
                int kb = i4 * 4;
                buf1[(kb + 0) * ZS + rr] = v.x;
                buf1[(kb + 1) * ZS + rr] = v.y;
                buf1[(kb + 2) * ZS + rr] = v.z;
                buf1[(kb + 3) * ZS + rr] = v.w;
            }
            __syncthreads();
            #pragma unroll 14
            for (int k = 0; k < 112; ++k) {
                float2 w = *(const float2*)&sWt[k * WS + ub];
                unsigned long long wx = pack2(w.x, w.x);
                unsigned long long wy = pack2(w.y, w.y);
                ulonglong2 zp = *(const ulonglong2*)&buf1[k * ZS + roff];
                ulonglong2 zq = *(const ulonglong2*)&buf1[k * ZS + roff + 4];
                a0[0] = fma2(zp.x, wx, a0[0]);  a0[1] = fma2(zp.y, wx, a0[1]);
                a0[2] = fma2(zq.x, wx, a0[2]);  a0[3] = fma2(zq.y, wx, a0[3]);
                a1[0] = fma2(zp.x, wy, a1[0]);  a1[1] = fma2(zp.y, wy, a1[1]);
                a1[2] = fma2(zq.x, wy, a1[2]);  a1[3] = fma2(zq.y, wy, a1[3]);
            }
            __syncthreads();
        }
        float bv0 = b_in[ub], bv1 = b_in[ub + 1];
        #pragma unroll
        for (int j = 0; j < 2; ++j) {
            unsigned long long* a = j ? a1 : a0;
            float bv = j ? bv1 : bv0;
            float2 t0 = unpack2(a[0]), t1 = unpack2(a[1]);
            float2 t2 = unpack2(a[2]), t3 = unpack2(a[3]);
            *(float4*)&bufX[(ub + j) * ZS + roff] =
                make_float4(t0.x + bv, t0.y + bv, t1.x + bv, t1.y + bv);
            *(float4*)&bufX[(ub + j) * ZS + roff + 4] =
                make_float4(t2.x + bv, t2.y + bv, t3.x + bv, t3.y + bv);
        }
        __syncthreads();
    }

    // =========== mma mainloop setup ===========
    const int lane = tid & 31;
    const int warp = tid >> 5;
    const int g    = lane >> 2;    // group id (0..7)
    const int t    = lane & 3;     // thread in group

    // x fragment (C layout): xf[mt][nt][e]; e: c0=(g,2t) c1=(g,2t+1) c2=(g+8,2t) c3=(g+8,2t+1)
    float xf[2][2][4];
    #pragma unroll
    for (int mt = 0; mt < 2; ++mt)
    #pragma unroll
    for (int nt = 0; nt < 2; ++nt) {
        int m0 = (warp * 2 + mt) * 16 + g;
        int n0 = nt * 8 + 2 * t;
        float2 v0 = *(const float2*)&bufX[m0 * ZS + n0];
        float2 v1 = *(const float2*)&bufX[(m0 + 8) * ZS + n0];
        xf[mt][nt][0] = v0.x;  xf[mt][nt][1] = v0.y;
        xf[mt][nt][2] = v1.x;  xf[mt][nt][3] = v1.y;
    }

    uint32_t wh[2][8][4];     // register-resident Wh fragments
    float zv[2][2][4];        // current z in C-fragment layout

    // producer store constants
    const int   l0 = 8 * t + (g >> 1);
    const uint32_t hb = (uint32_t)(g & 1) * 2;

    const float* Ws[4] = { W1, W2, W3, W4 };
    for (int blk = 0; blk < 4; ++blk) {
        const float* Wb = Ws[blk];

        // ---- load W fragments: Wh -> regs, Wl -> warp-private smem ----
        #pragma unroll
        for (int mt = 0; mt < 2; ++mt) {
            int MT = warp * 2 + mt;
            #pragma unroll
            for (int kt = 0; kt < 8; ++kt) {
                uint32_t wlv[4];
                #pragma unroll
                for (int r = 0; r < 4; ++r) {
                    int m  = MT * 16 + g + ((r & 1) << 3);
                    int kk = kt * 16 + ((r >> 1) << 3) + 2 * t;
                    float2 wv = *(const float2*)(Wb + m * 128 + kk);
                    uint32_t h = bfpack(wv.x, wv.y);
                    float e0 = wv.x - __uint_as_float(h << 16);
                    float e1 = wv.y - __uint_as_float(h & 0xFFFF0000u);
                    wh[mt][kt][r] = h;
                    wlv[r] = bfpack(e0, e1);
                }
                uint32_t wadr = sWls + (uint32_t)(((MT * 8 + kt) * 32 + lane) * 16);
                asm volatile("st.shared.v4.b32 [%0], {%1,%2,%3,%4};"
                             :: "r"(wadr), "r"(wlv[0]), "r"(wlv[1]), "r"(wlv[2]), "r"(wlv[3])
                             : "memory");
            }
        }

        // ---- z0 = tanh(x) -> ZB (hi/lo, B-fragment order) ----
        #pragma unroll
        for (int mt = 0; mt < 2; ++mt)
        #pragma unroll
        for (int nt = 0; nt < 2; ++nt) {
            #pragma unroll
            for (int e = 0; e < 4; ++e) zv[mt][nt][e] = fast_tanh(xf[mt][nt][e]);
        }
        #pragma unroll
        for (int mt = 0; mt < 2; ++mt)
        #pragma unroll
        for (int nt = 0; nt < 2; ++nt) {
            uint32_t base = (uint32_t)((((warp * 2 + mt) * 2 + nt) * 32) * 8);
            #pragma unroll
            for (int e = 0; e < 4; ++e) {
                float zz = zv[mt][nt][e];
                unsigned short h = f2bf(zz);
                float lo = zz - __uint_as_float(((uint32_t)h) << 16);
                unsigned short l = f2bf(lo);
                uint32_t off = base + (uint32_t)(((e & 1) ? l0 + 4 : l0) * 8)
                             + (uint32_t)((e >> 1) * 4) + hb;
                asm volatile("st.shared.b16 [%0], %1;" :: "r"(sZBh + off), "h"(h) : "memory");
                asm volatile("st.shared.b16 [%0], %1;" :: "r"(sZBl + off), "h"(l) : "memory");
            }
        }
        __syncthreads();

        // ---- Picard iterations via HMMA ----
        for (int it = 0; it < N_ITER; ++it) {
            float acc[2][2][4];
            #pragma unroll
            for (int mt = 0; mt < 2; ++mt)
            #pragma unroll
            for (int nt = 0; nt < 2; ++nt)
            #pragma unroll
            for (int e = 0; e < 4; ++e) acc[mt][nt][e] = xf[mt][nt][e];

            #pragma unroll
            for (int nt = 0; nt < 2; ++nt) {
                #pragma unroll
                for (int kt = 0; kt < 8; ++kt) {
                    uint32_t zh0, zh1, zl0, zl1;
                    uint32_t off = (uint32_t)(((kt * 2 + nt) * 32 + lane) * 8);
                    asm volatile("ld.shared.v2.b32 {%0,%1}, [%2];"
                                 : "=r"(zh0), "=r"(zh1) : "r"(sZBh + off));
                    asm volatile("ld.shared.v2.b32 {%0,%1}, [%2];"
                                 : "=r"(zl0), "=r"(zl1) : "r"(sZBl + off));
                    #pragma unroll
                    for (int mt = 0; mt < 2; ++mt) {
                        uint32_t wl0, wl1, wl2, wl3;
                        uint32_t wadr = sWls +
                            (uint32_t)((((warp * 2 + mt) * 8 + kt) * 32 + lane) * 16);
                        asm volatile("ld.shared.v4.b32 {%0,%1,%2,%3}, [%4];"
                                     : "=r"(wl0), "=r"(wl1), "=r"(wl2), "=r"(wl3)
                                     : "r"(wadr));
                        mma_bf16(acc[mt][nt], wh[mt][kt][0], wh[mt][kt][1],
                                 wh[mt][kt][2], wh[mt][kt][3], zh0, zh1);
                        mma_bf16(acc[mt][nt], wh[mt][kt][0], wh[mt][kt][1],
                                 wh[mt][kt][2], wh[mt][kt][3], zl0, zl1);
                        mma_bf16(acc[mt][nt], wl0, wl1, wl2, wl3, zh0, zh1);
                    }
                }
            }

            #pragma unroll
            for (int mt = 0; mt < 2; ++mt)
            #pragma unroll
            for (int nt = 0; nt < 2; ++nt)
            #pragma unroll
            for (int e = 0; e < 4; ++e)
                zv[mt][nt][e] = fast_tanh(acc[mt][nt][e]);

            __syncthreads();   // everyone done reading ZB

            if (it < N_ITER - 1) {
                #pragma unroll
                for (int mt = 0; mt < 2; ++mt)
                #pragma unroll
                for (int nt = 0; nt < 2; ++nt) {
                    uint32_t base = (uint32_t)((((warp * 2 + mt) * 2 + nt) * 32) * 8);
                    #pragma unroll
                    for (int e = 0; e < 4; ++e) {
                        float zz = zv[mt][nt][e];
                        unsigned short h = f2bf(zz);
                        float lo = zz - __uint_as_float(((uint32_t)h) << 16);
                        unsigned short l = f2bf(lo);
                        uint32_t off = base + (uint32_t)(((e & 1) ? l0 + 4 : l0) * 8)
                                     + (uint32_t)((e >> 1) * 4) + hb;
                        asm volatile("st.shared.b16 [%0], %1;" :: "r"(sZBh + off), "h"(h) : "memory");
                        asm volatile("st.shared.b16 [%0], %1;" :: "r"(sZBl + off), "h"(l) : "memory");
                    }
                }
                __syncthreads();
            }
        }

        // block output -> next block input (fragment layout, registers)
        #pragma unroll
        for (int mt = 0; mt < 2; ++mt)
        #pragma unroll
        for (int nt = 0; nt < 2; ++nt)
        #pragma unroll
        for (int e = 0; e < 4; ++e) xf[mt][nt][e] = zv[mt][nt][e];
    }

    // ---- write final z (fragment layout) to bufX fp32 ----
    #pragma unroll
    for (int mt = 0; mt < 2; ++mt)
    #pragma unroll
    for (int nt = 0; nt < 2; ++nt) {
        int m0 = (warp * 2 + mt) * 16 + g;
        int n0 = nt * 8 + 2 * t;
        *(float2*)&bufX[m0 * ZS + n0]       = make_float2(zv[mt][nt][0], zv[mt][nt][1]);
        *(float2*)&bufX[(m0 + 8) * ZS + n0] = make_float2(zv[mt][nt][2], zv[mt][nt][3]);
    }
    __syncthreads();

    // =========== Phase 5: logits + softmax ===========
    for (int idx = tid; idx < 10 * UNITS; idx += NTHREADS) sWt[idx] = W_out[idx];
    if (tid < 10) sWt[1280 + tid] = b_out[tid];
    __syncthreads();
    float* slog = sWt + 1296;
    for (int idx = tid; idx < 160; idx += NTHREADS) {
        int o = idx >> 4;
        int r = idx & 15;
        float acc = sWt[1280 + o];
        #pragma unroll 8
        for (int k = 0; k < UNITS; ++k)
            acc += bufX[k * ZS + r] * sWt[o * UNITS + k];
        slog[o * 16 + r] = acc;
    }
    __syncthreads();
    if (tid < ROWS_PER_CTA) {
        int r = tid;
        float l[10];
        float m = -INFINITY;
        #pragma unroll
        for (int o = 0; o < 10; ++o) { l[o] = slog[o * 16 + r]; m = fmaxf(m, l[o]); }
        float s = 0.f;
        #pragma unroll
        for (int o = 0; o < 10; ++o) { l[o] = expf(l[o] - m); s += l[o]; }
        float inv = 1.f / s;
        #pragma unroll
        for (int o = 0; o < 10; ++o) out[(row0 + r) * 10 + o] = l[o] * inv;
    }
}

extern "C" void kernel_launch(void* const* d_in, const int* in_sizes, int n_in,
                              void* d_out, int out_size)
{
    const float* x     = (const float*)d_in[0];
    const float* W_in  = (const float*)d_in[1];
    const float* b_in  = (const float*)d_in[2];
    const float* W1    = (const float*)d_in[3];
    const float* W2    = (const float*)d_in[4];
    const float* W3    = (const float*)d_in[5];
    const float* W4    = (const float*)d_in[6];
    const float* W_out = (const float*)d_in[7];
    const float* b_out = (const float*)d_in[8];
    float* out = (float*)d_out;

    cudaFuncSetAttribute(newton_net_kernel,
                         cudaFuncAttributeMaxDynamicSharedMemorySize, SMEM_BYTES);

    newton_net_kernel<<<NCTA, NTHREADS, SMEM_BYTES>>>(
        x, W_in, b_in, W1, W2, W3, W4, W_out, b_out, out);
}

// round 6
// speedup vs baseline: 7.9904x; 1.1268x over previous
#include <cuda_runtime.h>
#include <math.h>
#include <stdint.h>

#define UNITS     128
#define N_ITER    15
#define ZS        20     // phase0 x-tile stride (floats)
#define WS        130    // phase0 W^T stride (floats)

// ---- kernel1 (phase0) smem ----
#define K1_SWT_FLOATS  (112 * WS)          // 14560
#define K1_BUF1_OFF    (112 * WS)
#define K1_SMEM_FLOATS (112 * WS + 112 * ZS)
#define K1_SMEM_BYTES  (K1_SMEM_FLOATS * 4)

// ---- kernel2 (blocks + epilogue) smem (bytes) ----
#define BXS        10            // bufX stride floats (8 rows + 2 pad, 8B aligned)
#define BUFX2_BYTE 0             // 128*10*4 = 5120
#define ZBH2_BYTE  5120          // 2048
#define ZBL2_BYTE  7168          // 2048
#define WLS2_BYTE  9216          // 32768
#define K2_SMEM_BYTES 41984

__device__ float g_xb[2048 * 128];   // phase0 output scratch [row][unit]

__device__ __forceinline__ uint32_t smem_u32(const void* p) {
    uint32_t a;
    asm("{ .reg .u64 t; cvta.to.shared.u64 t, %1; cvt.u32.u64 %0, t; }" : "=r"(a) : "l"(p));
    return a;
}
__device__ __forceinline__ unsigned long long pack2(float lo, float hi) {
    unsigned long long r;
    asm("mov.b64 %0, {%1, %2};" : "=l"(r) : "f"(lo), "f"(hi));
    return r;
}
__device__ __forceinline__ float2 unpack2(unsigned long long v) {
    float2 f;
    asm("mov.b64 {%0, %1}, %2;" : "=f"(f.x), "=f"(f.y) : "l"(v));
    return f;
}
__device__ __forceinline__ unsigned long long fma2(unsigned long long a,
                                                   unsigned long long b,
                                                   unsigned long long c) {
    unsigned long long d;
    asm("fma.rn.f32x2 %0, %1, %2, %3;" : "=l"(d) : "l"(a), "l"(b), "l"(c));
    return d;
}
__device__ __forceinline__ float fast_tanh(float x) {
    float e, r;
    asm("ex2.approx.f32 %0, %1;" : "=f"(e) : "f"(x * 2.8853900817779268f));
    asm("rcp.approx.f32 %0, %1;" : "=f"(r) : "f"(e + 1.0f));
    return fmaf(-2.0f, r, 1.0f);
}
__device__ __forceinline__ uint32_t bfpack(float lo, float hi) {
    uint32_t r;
    asm("cvt.rn.bf16x2.f32 %0, %1, %2;" : "=r"(r) : "f"(hi), "f"(lo));
    return r;
}
__device__ __forceinline__ unsigned short f2bf(float f) {
    unsigned short h;
    asm("cvt.rn.bf16.f32 %0, %1;" : "=h"(h) : "f"(f));
    return h;
}
__device__ __forceinline__ void mma_bf16(float* c,
                                         uint32_t a0, uint32_t a1, uint32_t a2, uint32_t a3,
                                         uint32_t b0, uint32_t b1) {
    asm volatile(
        "mma.sync.aligned.m16n8k16.row.col.f32.bf16.bf16.f32 "
        "{%0,%1,%2,%3}, {%4,%5,%6,%7}, {%8,%9}, {%0,%1,%2,%3};"
        : "+f"(c[0]), "+f"(c[1]), "+f"(c[2]), "+f"(c[3])
        : "r"(a0), "r"(a1), "r"(a2), "r"(a3), "r"(b0), "r"(b1));
}

extern __shared__ float smem[];

// ================== Kernel 1: xb = x @ W_in^T + b_in ==================
// grid 128 CTAs x 16 rows, 256 threads (thread = 1 unit x 8 rows)
__global__ __launch_bounds__(256, 1)
void phase0_kernel(const float* __restrict__ x,
                   const float* __restrict__ W_in,
                   const float* __restrict__ b_in)
{
    float* sWt  = smem;
    float* buf1 = smem + K1_BUF1_OFF;

    const int tid  = threadIdx.x;
    const int u    = tid & 127;
    const int g    = tid >> 7;
    const int roff = g * 8;
    const int row0 = blockIdx.x * 16;

    unsigned long long a[4] = {0ull, 0ull, 0ull, 0ull};

    for (int kt = 0; kt < 7; ++kt) {
        for (int idx = tid; idx < 128 * 28; idx += 256) {
            int uu = idx / 28;
            int i4 = idx - uu * 28;
            float4 v = *(const float4*)(W_in + uu * 784 + kt * 112 + i4 * 4);
            int kb = i4 * 4;
            sWt[(kb + 0) * WS + uu] = v.x;
            sWt[(kb + 1) * WS + uu] = v.y;
            sWt[(kb + 2) * WS + uu] = v.z;
            sWt[(kb + 3) * WS + uu] = v.w;
        }
        for (int idx = tid; idx < 16 * 28; idx += 256) {
            int rr = idx / 28;
            int i4 = idx - rr * 28;
            float4 v = *(const float4*)(x + (row0 + rr) * 784 + kt * 112 + i4 * 4);
            int kb = i4 * 4;
            buf1[(kb + 0) * ZS + rr] = v.x;
            buf1[(kb + 1) * ZS + rr] = v.y;
            buf1[(kb + 2) * ZS + rr] = v.z;
            buf1[(kb + 3) * ZS + rr] = v.w;
        }
        __syncthreads();
        #pragma unroll 16
        for (int k = 0; k < 112; ++k) {
            float w = sWt[k * WS + u];
            unsigned long long wv = pack2(w, w);
            ulonglong2 zp = *(const ulonglong2*)&buf1[k * ZS + roff];
            ulonglong2 zq = *(const ulonglong2*)&buf1[k * ZS + roff + 4];
            a[0] = fma2(zp.x, wv, a[0]);
            a[1] = fma2(zp.y, wv, a[1]);
            a[2] = fma2(zq.x, wv, a[2]);
            a[3] = fma2(zq.y, wv, a[3]);
        }
        __syncthreads();
    }
    float bv = b_in[u];
    #pragma unroll
    for (int i = 0; i < 4; ++i) {
        float2 t = unpack2(a[i]);
        g_xb[(row0 + roff + 2 * i) * 128 + u]     = t.x + bv;
        g_xb[(row0 + roff + 2 * i + 1) * 128 + u] = t.y + bv;
    }
}

// ================== Kernel 2: 4 implicit blocks + softmax ==================
// grid 256 CTAs x 8 rows, 128 threads
__global__ __launch_bounds__(128, 2)
void blocks_kernel(const float* __restrict__ W1,
                   const float* __restrict__ W2,
                   const float* __restrict__ W3,
                   const float* __restrict__ W4,
                   const float* __restrict__ W_out,
                   const float* __restrict__ b_out,
                   float* __restrict__ out)
{
    const int tid  = threadIdx.x;
    const int row0 = blockIdx.x * 8;

    char* smem_c = (char*)smem;
    const uint32_t sbase = smem_u32(smem);
    const uint32_t sZBh  = sbase + ZBH2_BYTE;
    const uint32_t sZBl  = sbase + ZBL2_BYTE;
    const uint32_t sWls  = sbase + WLS2_BYTE;

    float* bufX = (float*)(smem_c + BUFX2_BYTE);    // [u*BXS + r] fp32
    float* sEpi = (float*)(smem_c + WLS2_BYTE);     // epilogue reuse

    // load this CTA's 8 rows of xb (coalesced) into bufX transposed
    for (int idx = tid; idx < 8 * 128; idx += 128) {
        int r = idx >> 7;
        int u = idx & 127;
        bufX[u * BXS + r] = g_xb[(row0 + r) * 128 + u];
    }
    __syncthreads();

    const int lane = tid & 31;
    const int warp = tid >> 5;
    const int g    = lane >> 2;
    const int t    = lane & 3;

    // x fragments: xf[mt][e]; e: c0=(g,2t) c1=(g,2t+1) c2=(g+8,2t) c3=(g+8,2t+1)
    float xf[2][4];
    #pragma unroll
    for (int mt = 0; mt < 2; ++mt) {
        int m0 = (warp * 2 + mt) * 16 + g;
        int n0 = 2 * t;
        float2 v0 = *(const float2*)&bufX[m0 * BXS + n0];
        float2 v1 = *(const float2*)&bufX[(m0 + 8) * BXS + n0];
        xf[mt][0] = v0.x;  xf[mt][1] = v0.y;
        xf[mt][2] = v1.x;  xf[mt][3] = v1.y;
    }

    uint32_t wh[2][8][4];
    float zv[2][4];

    const int      l0 = 8 * t + (g >> 1);
    const uint32_t hb = (uint32_t)(g & 1) * 2;

    const float* Ws[4] = { W1, W2, W3, W4 };
    for (int blk = 0; blk < 4; ++blk) {
        const float* Wb = Ws[blk];

        // ---- W fragments: Wh -> regs, Wl -> warp-private smem ----
        #pragma unroll
        for (int mt = 0; mt < 2; ++mt) {
            int MT = warp * 2 + mt;
            #pragma unroll
            for (int kt = 0; kt < 8; ++kt) {
                uint32_t wlv[4];
                #pragma unroll
                for (int r = 0; r < 4; ++r) {
                    int m  = MT * 16 + g + ((r & 1) << 3);
                    int kk = kt * 16 + ((r >> 1) << 3) + 2 * t;
                    float2 wv = *(const float2*)(Wb + m * 128 + kk);
                    uint32_t h = bfpack(wv.x, wv.y);
                    float e0 = wv.x - __uint_as_float(h << 16);
                    float e1 = wv.y - __uint_as_float(h & 0xFFFF0000u);
                    wh[mt][kt][r] = h;
                    wlv[r] = bfpack(e0, e1);
                }
                uint32_t wadr = sWls + (uint32_t)(((MT * 8 + kt) * 32 + lane) * 16);
                asm volatile("st.shared.v4.b32 [%0], {%1,%2,%3,%4};"
                             :: "r"(wadr), "r"(wlv[0]), "r"(wlv[1]), "r"(wlv[2]), "r"(wlv[3])
                             : "memory");
            }
        }

        // ---- z0 = tanh(x) -> ZB hi/lo (B-fragment order) ----
        #pragma unroll
        for (int mt = 0; mt < 2; ++mt)
        #pragma unroll
        for (int e = 0; e < 4; ++e) zv[mt][e] = fast_tanh(xf[mt][e]);

        #pragma unroll
        for (int mt = 0; mt < 2; ++mt) {
            uint32_t base = (uint32_t)((warp * 2 + mt) * 256);
            #pragma unroll
            for (int e = 0; e < 4; ++e) {
                float zz = zv[mt][e];
                unsigned short h = f2bf(zz);
                float lo = zz - __uint_as_float(((uint32_t)h) << 16);
                unsigned short l = f2bf(lo);
                uint32_t off = base + (uint32_t)(((e & 1) ? l0 + 4 : l0) * 8)
                             + (uint32_t)((e >> 1) * 4) + hb;
                asm volatile("st.shared.b16 [%0], %1;" :: "r"(sZBh + off), "h"(h) : "memory");
                asm volatile("st.shared.b16 [%0], %1;" :: "r"(sZBl + off), "h"(l) : "memory");
            }
        }
        __syncthreads();

        // ---- Picard iterations via HMMA ----
        for (int it = 0; it < N_ITER; ++it) {
            float acc[2][4];
            #pragma unroll
            for (int mt = 0; mt < 2; ++mt)
            #pragma unroll
            for (int e = 0; e < 4; ++e) acc[mt][e] = xf[mt][e];

            #pragma unroll
            for (int kt = 0; kt < 8; ++kt) {
                uint32_t zh0, zh1, zl0, zl1;
                uint32_t off = (uint32_t)((kt * 32 + lane) * 8);
                asm volatile("ld.shared.v2.b32 {%0,%1}, [%2];"
                             : "=r"(zh0), "=r"(zh1) : "r"(sZBh + off));
                asm volatile("ld.shared.v2.b32 {%0,%1}, [%2];"
                             : "=r"(zl0), "=r"(zl1) : "r"(sZBl + off));
                #pragma unroll
                for (int mt = 0; mt < 2; ++mt) {
                    uint32_t wl0, wl1, wl2, wl3;
                    uint32_t wadr = sWls +
                        (uint32_t)((((warp * 2 + mt) * 8 + kt) * 32 + lane) * 16);
                    asm volatile("ld.shared.v4.b32 {%0,%1,%2,%3}, [%4];"
                                 : "=r"(wl0), "=r"(wl1), "=r"(wl2), "=r"(wl3)
                                 : "r"(wadr));
                    mma_bf16(acc[mt], wh[mt][kt][0], wh[mt][kt][1],
                             wh[mt][kt][2], wh[mt][kt][3], zh0, zh1);
                    mma_bf16(acc[mt], wh[mt][kt][0], wh[mt][kt][1],
                             wh[mt][kt][2], wh[mt][kt][3], zl0, zl1);
                    mma_bf16(acc[mt], wl0, wl1, wl2, wl3, zh0, zh1);
                }
            }

            #pragma unroll
            for (int mt = 0; mt < 2; ++mt)
            #pragma unroll
            for (int e = 0; e < 4; ++e)
                zv[mt][e] = fast_tanh(acc[mt][e]);

            __syncthreads();   // all reads of ZB complete

            if (it < N_ITER - 1) {
                #pragma unroll
                for (int mt = 0; mt < 2; ++mt) {
                    uint32_t base = (uint32_t)((warp * 2 + mt) * 256);
                    #pragma unroll
                    for (int e = 0; e < 4; ++e) {
                        float zz = zv[mt][e];
                        unsigned short h = f2bf(zz);
                        float lo = zz - __uint_as_float(((uint32_t)h) << 16);
                        unsigned short l = f2bf(lo);
                        uint32_t off = base + (uint32_t)(((e & 1) ? l0 + 4 : l0) * 8)
                                     + (uint32_t)((e >> 1) * 4) + hb;
                        asm volatile("st.shared.b16 [%0], %1;" :: "r"(sZBh + off), "h"(h) : "memory");
                        asm volatile("st.shared.b16 [%0], %1;" :: "r"(sZBl + off), "h"(l) : "memory");
                    }
                }
                __syncthreads();
            }
        }

        #pragma unroll
        for (int mt = 0; mt < 2; ++mt)
        #pragma unroll
        for (int e = 0; e < 4; ++e) xf[mt][e] = zv[mt][e];
    }

    // ---- final z -> bufX ----
    #pragma unroll
    for (int mt = 0; mt < 2; ++mt) {
        int m0 = (warp * 2 + mt) * 16 + g;
        int n0 = 2 * t;
        *(float2*)&bufX[m0 * BXS + n0]       = make_float2(zv[mt][0], zv[mt][1]);
        *(float2*)&bufX[(m0 + 8) * BXS + n0] = make_float2(zv[mt][2], zv[mt][3]);
    }
    __syncthreads();

    // ---- epilogue: logits + softmax (8 rows) ----
    for (int idx = tid; idx < 10 * UNITS; idx += 128) sEpi[idx] = W_out[idx];
    if (tid < 10) sEpi[1280 + tid] = b_out[tid];
    __syncthreads();
    float* slog = sEpi + 1296;   // [o][r], 80 floats
    if (tid < 80) {
        int o = tid >> 3;
        int r = tid & 7;
        float acc = sEpi[1280 + o];
        #pragma unroll 8
        for (int k = 0; k < UNITS; ++k)
            acc += bufX[k * BXS + r] * sEpi[o * UNITS + k];
        slog[o * 8 + r] = acc;
    }
    __syncthreads();
    if (tid < 8) {
        int r = tid;
        float l[10];
        float m = -INFINITY;
        #pragma unroll
        for (int o = 0; o < 10; ++o) { l[o] = slog[o * 8 + r]; m = fmaxf(m, l[o]); }
        float s = 0.f;
        #pragma unroll
        for (int o = 0; o < 10; ++o) { l[o] = expf(l[o] - m); s += l[o]; }
        float inv = 1.f / s;
        #pragma unroll
        for (int o = 0; o < 10; ++o) out[(row0 + r) * 10 + o] = l[o] * inv;
    }
}

extern "C" void kernel_launch(void* const* d_in, const int* in_sizes, int n_in,
                              void* d_out, int out_size)
{
    const float* x     = (const float*)d_in[0];
    const float* W_in  = (const float*)d_in[1];
    const float* b_in  = (const float*)d_in[2];
    const float* W1    = (const float*)d_in[3];
    const float* W2    = (const float*)d_in[4];
    const float* W3    = (const float*)d_in[5];
    const float* W4    = (const float*)d_in[6];
    const float* W_out = (const float*)d_in[7];
    const float* b_out = (const float*)d_in[8];
    float* out = (float*)d_out;

    cudaFuncSetAttribute(phase0_kernel,
                         cudaFuncAttributeMaxDynamicSharedMemorySize, K1_SMEM_BYTES);
    cudaFuncSetAttribute(blocks_kernel,
                         cudaFuncAttributeMaxDynamicSharedMemorySize, K2_SMEM_BYTES);

    phase0_kernel<<<128, 256, K1_SMEM_BYTES>>>(x, W_in, b_in);
    blocks_kernel<<<256, 128, K2_SMEM_BYTES>>>(W1, W2, W3, W4, W_out, b_out, out);
}

// round 7
// speedup vs baseline: 10.8078x; 1.3526x over previous
#include <cuda_runtime.h>
#include <math.h>
#include <stdint.h>

#define UNITS     128
#define N_ITER    12
#define BXS       10

// ---- blocks_kernel smem (bytes) ----
#define BUFX_BYTE  0         // 128*10*4 = 5120
#define ZBH0_BYTE  5120
#define ZBL0_BYTE  7168
#define ZBH1_BYTE  9216
#define ZBL1_BYTE  11264
#define WLS_BYTE   13312     // 32768
#define K2_SMEM_BYTES 46080

// pre-split weights (bf16 raw bits): W_in [128*784], then W1..W4 [128*128] each
#define WIN_ELEMS  (128 * 784)
#define WB_ELEMS   (128 * 128)
#define TOT_ELEMS  (WIN_ELEMS + 4 * WB_ELEMS)
__device__ unsigned short g_wh[TOT_ELEMS];
__device__ unsigned short g_wl[TOT_ELEMS];

__device__ __forceinline__ uint32_t smem_u32(const void* p) {
    uint32_t a;
    asm("{ .reg .u64 t; cvta.to.shared.u64 t, %1; cvt.u32.u64 %0, t; }" : "=r"(a) : "l"(p));
    return a;
}
__device__ __forceinline__ float fast_tanh(float x) {
    float e, r;
    asm("ex2.approx.f32 %0, %1;" : "=f"(e) : "f"(x * 2.8853900817779268f));
    asm("rcp.approx.f32 %0, %1;" : "=f"(r) : "f"(e + 1.0f));
    return fmaf(-2.0f, r, 1.0f);
}
__device__ __forceinline__ uint32_t bfpack(float lo, float hi) {
    uint32_t r;
    asm("cvt.rn.bf16x2.f32 %0, %1, %2;" : "=r"(r) : "f"(hi), "f"(lo));
    return r;
}
__device__ __forceinline__ unsigned short f2bf(float f) {
    unsigned short h;
    asm("cvt.rn.bf16.f32 %0, %1;" : "=h"(h) : "f"(f));
    return h;
}
__device__ __forceinline__ void mma_bf16(float* c,
                                         uint32_t a0, uint32_t a1, uint32_t a2, uint32_t a3,
                                         uint32_t b0, uint32_t b1) {
    asm volatile(
        "mma.sync.aligned.m16n8k16.row.col.f32.bf16.bf16.f32 "
        "{%0,%1,%2,%3}, {%4,%5,%6,%7}, {%8,%9}, {%0,%1,%2,%3};"
        : "+f"(c[0]), "+f"(c[1]), "+f"(c[2]), "+f"(c[3])
        : "r"(a0), "r"(a1), "r"(a2), "r"(a3), "r"(b0), "r"(b1));
}

extern __shared__ float smem[];

// ================== Prep: split weights into bf16 hi/lo ==================
__global__ __launch_bounds__(256, 4)
void split_kernel(const float* __restrict__ W_in,
                  const float* __restrict__ W1,
                  const float* __restrict__ W2,
                  const float* __restrict__ W3,
                  const float* __restrict__ W4)
{
    int i = blockIdx.x * 256 + threadIdx.x;
    if (i >= TOT_ELEMS) return;
    float v;
    if (i < WIN_ELEMS) {
        v = W_in[i];
    } else {
        int j = i - WIN_ELEMS;
        int b = j >> 14;
        int o = j & (WB_ELEMS - 1);
        v = (b == 0 ? W1 : b == 1 ? W2 : b == 2 ? W3 : W4)[o];
    }
    unsigned short h = f2bf(v);
    float lo = v - __uint_as_float(((uint32_t)h) << 16);
    g_wh[i] = h;
    g_wl[i] = f2bf(lo);
}

// ================== Main: phase0 + 4 implicit blocks + softmax ==================
// grid 256 CTAs x 8 rows, 128 threads
__global__ __launch_bounds__(128, 2)
void blocks_kernel(const float* __restrict__ x,
                   const float* __restrict__ b_in,
                   const float* __restrict__ W_out,
                   const float* __restrict__ b_out,
                   float* __restrict__ out)
{
    const int tid  = threadIdx.x;
    const int row0 = blockIdx.x * 8;

    char* smem_c = (char*)smem;
    const uint32_t sbase = smem_u32(smem);
    const uint32_t sWls  = sbase + WLS_BYTE;

    float* bufX = (float*)(smem_c + BUFX_BYTE);
    float* sEpi = (float*)(smem_c + WLS_BYTE);

    const int lane = tid & 31;
    const int warp = tid >> 5;
    const int g    = lane >> 2;
    const int t    = lane & 3;

    const int      l0 = 8 * t + (g >> 1);
    const uint32_t hb = (uint32_t)(g & 1) * 2;

    // =========== Phase 0 (fused): xf = x @ W_in^T + b_in via HMMA ===========
    float xf[2][4];
    #pragma unroll
    for (int mt = 0; mt < 2; ++mt) {
        int m = (warp * 2 + mt) * 16 + g;
        float b0 = b_in[m], b1 = b_in[m + 8];
        xf[mt][0] = b0;  xf[mt][1] = b0;
        xf[mt][2] = b1;  xf[mt][3] = b1;
    }
    {
        const float* xp_base = x + (row0 + g) * 784 + 2 * t;
        #pragma unroll 7
        for (int kt = 0; kt < 49; ++kt) {
            const int k0 = kt * 16;
            float2 xv0 = *(const float2*)(xp_base + k0);
            float2 xv1 = *(const float2*)(xp_base + k0 + 8);
            uint32_t bh0 = bfpack(xv0.x, xv0.y);
            uint32_t bh1 = bfpack(xv1.x, xv1.y);
            float e0 = xv0.x - __uint_as_float(bh0 << 16);
            float e1 = xv0.y - __uint_as_float(bh0 & 0xFFFF0000u);
            float e2 = xv1.x - __uint_as_float(bh1 << 16);
            float e3 = xv1.y - __uint_as_float(bh1 & 0xFFFF0000u);
            uint32_t bl0 = bfpack(e0, e1);
            uint32_t bl1 = bfpack(e2, e3);
            #pragma unroll
            for (int mt = 0; mt < 2; ++mt) {
                uint32_t ah[4], al[4];
                #pragma unroll
                for (int r = 0; r < 4; ++r) {
                    int m  = (warp * 2 + mt) * 16 + g + ((r & 1) << 3);
                    int kk = k0 + ((r >> 1) << 3) + 2 * t;
                    ah[r] = *(const uint32_t*)&g_wh[m * 784 + kk];
                    al[r] = *(const uint32_t*)&g_wl[m * 784 + kk];
                }
                mma_bf16(xf[mt], ah[0], ah[1], ah[2], ah[3], bh0, bh1);
                mma_bf16(xf[mt], ah[0], ah[1], ah[2], ah[3], bl0, bl1);
                mma_bf16(xf[mt], al[0], al[1], al[2], al[3], bh0, bh1);
            }
        }
    }

    // =========== 4 implicit blocks ===========
    uint32_t wh[2][8][4];
    float zv[2][4];

    for (int blk = 0; blk < 4; ++blk) {
        const unsigned short* whb = g_wh + WIN_ELEMS + blk * WB_ELEMS;
        const unsigned short* wlb = g_wl + WIN_ELEMS + blk * WB_ELEMS;

        // ---- W fragments: Wh -> regs, Wl -> warp-private smem ----
        #pragma unroll
        for (int mt = 0; mt < 2; ++mt) {
            int MT = warp * 2 + mt;
            #pragma unroll
            for (int kt = 0; kt < 8; ++kt) {
                uint32_t wlv[4];
                #pragma unroll
                for (int r = 0; r < 4; ++r) {
                    int m  = MT * 16 + g + ((r & 1) << 3);
                    int kk = kt * 16 + ((r >> 1) << 3) + 2 * t;
                    wh[mt][kt][r] = *(const uint32_t*)&whb[m * 128 + kk];
                    wlv[r]        = *(const uint32_t*)&wlb[m * 128 + kk];
                }
                uint32_t wadr = sWls + (uint32_t)(((MT * 8 + kt) * 32 + lane) * 16);
                asm volatile("st.shared.v4.b32 [%0], {%1,%2,%3,%4};"
                             :: "r"(wadr), "r"(wlv[0]), "r"(wlv[1]), "r"(wlv[2]), "r"(wlv[3])
                             : "memory");
            }
        }

        // ---- z0 = tanh(x) -> ZB buffer 0 ----
        #pragma unroll
        for (int mt = 0; mt < 2; ++mt)
        #pragma unroll
        for (int e = 0; e < 4; ++e) zv[mt][e] = fast_tanh(xf[mt][e]);

        #pragma unroll
        for (int mt = 0; mt < 2; ++mt) {
            uint32_t base = (uint32_t)((warp * 2 + mt) * 256);
            #pragma unroll
            for (int e = 0; e < 4; ++e) {
                float zz = zv[mt][e];
                unsigned short h = f2bf(zz);
                float lo = zz - __uint_as_float(((uint32_t)h) << 16);
                unsigned short l = f2bf(lo);
                uint32_t off = base + (uint32_t)(((e & 1) ? l0 + 4 : l0) * 8)
                             + (uint32_t)((e >> 1) * 4) + hb;
                asm volatile("st.shared.b16 [%0], %1;" :: "r"(sbase + ZBH0_BYTE + off), "h"(h) : "memory");
                asm volatile("st.shared.b16 [%0], %1;" :: "r"(sbase + ZBL0_BYTE + off), "h"(l) : "memory");
            }
        }
        __syncthreads();

        // ---- Picard iterations, ping-pong ZB, 1 barrier/iter ----
        for (int it = 0; it < N_ITER; ++it) {
            const uint32_t rb = (it & 1) ? 4096u : 0u;   // read buffer offset
            const uint32_t wb = (it & 1) ? 0u : 4096u;   // write buffer offset
            float acc[2][4];
            #pragma unroll
            for (int mt = 0; mt < 2; ++mt)
            #pragma unroll
            for (int e = 0; e < 4; ++e) acc[mt][e] = xf[mt][e];

            #pragma unroll
            for (int kt = 0; kt < 8; ++kt) {
                uint32_t zh0, zh1, zl0, zl1;
                uint32_t off = (uint32_t)((kt * 32 + lane) * 8);
                asm volatile("ld.shared.v2.b32 {%0,%1}, [%2];"
                             : "=r"(zh0), "=r"(zh1) : "r"(sbase + ZBH0_BYTE + rb + off));
                asm volatile("ld.shared.v2.b32 {%0,%1}, [%2];"
                             : "=r"(zl0), "=r"(zl1) : "r"(sbase + ZBL0_BYTE + rb + off));
                #pragma unroll
                for (int mt = 0; mt < 2; ++mt) {
                    uint32_t wl0, wl1, wl2, wl3;
                    uint32_t wadr = sWls +
                        (uint32_t)((((warp * 2 + mt) * 8 + kt) * 32 + lane) * 16);
                    asm volatile("ld.shared.v4.b32 {%0,%1,%2,%3}, [%4];"
                                 : "=r"(wl0), "=r"(wl1), "=r"(wl2), "=r"(wl3)
                                 : "r"(wadr));
                    mma_bf16(acc[mt], wh[mt][kt][0], wh[mt][kt][1],
                             wh[mt][kt][2], wh[mt][kt][3], zh0, zh1);
                    mma_bf16(acc[mt], wh[mt][kt][0], wh[mt][kt][1],
                             wh[mt][kt][2], wh[mt][kt][3], zl0, zl1);
                    mma_bf16(acc[mt], wl0, wl1, wl2, wl3, zh0, zh1);
                }
            }

            #pragma unroll
            for (int mt = 0; mt < 2; ++mt)
            #pragma unroll
            for (int e = 0; e < 4; ++e)
                zv[mt][e] = fast_tanh(acc[mt][e]);

            if (it < N_ITER - 1) {
                #pragma unroll
                for (int mt = 0; mt < 2; ++mt) {
                    uint32_t base = (uint32_t)((warp * 2 + mt) * 256);
                    #pragma unroll
                    for (int e = 0; e < 4; ++e) {
                        float zz = zv[mt][e];
                        unsigned short h = f2bf(zz);
                        float lo = zz - __uint_as_float(((uint32_t)h) << 16);
                        unsigned short l = f2bf(lo);
                        uint32_t off = base + (uint32_t)(((e & 1) ? l0 + 4 : l0) * 8)
                                     + (uint32_t)((e >> 1) * 4) + hb;
                        asm volatile("st.shared.b16 [%0], %1;"
                                     :: "r"(sbase + ZBH0_BYTE + wb + off), "h"(h) : "memory");
                        asm volatile("st.shared.b16 [%0], %1;"
                                     :: "r"(sbase + ZBL0_BYTE + wb + off), "h"(l) : "memory");
                    }
                }
                __syncthreads();
            }
        }

        #pragma unroll
        for (int mt = 0; mt < 2; ++mt)
        #pragma unroll
        for (int e = 0; e < 4; ++e) xf[mt][e] = zv[mt][e];
        __syncthreads();   // all ZB reads done before next block's z0 store
    }

    // ---- final z -> bufX ----
    #pragma unroll
    for (int mt = 0; mt < 2; ++mt) {
        int m0 = (warp * 2 + mt) * 16 + g;
        int n0 = 2 * t;
        *(float2*)&bufX[m0 * BXS + n0]       = make_float2(zv[mt][0], zv[mt][1]);
        *(float2*)&bufX[(m0 + 8) * BXS + n0] = make_float2(zv[mt][2], zv[mt][3]);
    }
    __syncthreads();

    // ---- epilogue: logits + softmax (8 rows) ----
    for (int idx = tid; idx < 10 * UNITS; idx += 128) sEpi[idx] = W_out[idx];
    if (tid < 10) sEpi[1280 + tid] = b_out[tid];
    __syncthreads();
    float* slog = sEpi + 1296;   // [o][r], 80 floats
    if (tid < 80) {
        int o = tid >> 3;
        int r = tid & 7;
        float acc = sEpi[1280 + o];
        #pragma unroll 8
        for (int k = 0; k < UNITS; ++k)
            acc += bufX[k * BXS + r] * sEpi[o * UNITS + k];
        slog[o * 8 + r] = acc;
    }
    __syncthreads();
    if (tid < 8) {
        int r = tid;
        float l[10];
        float m = -INFINITY;
        #pragma unroll
        for (int o = 0; o < 10; ++o) { l[o] = slog[o * 8 + r]; m = fmaxf(m, l[o]); }
        float s = 0.f;
        #pragma unroll
        for (int o = 0; o < 10; ++o) { l[o] = expf(l[o] - m); s += l[o]; }
        float inv = 1.f / s;
        #pragma unroll
        for (int o = 0; o < 10; ++o) out[(row0 + r) * 10 + o] = l[o] * inv;
    }
}

extern "C" void kernel_launch(void* const* d_in, const int* in_sizes, int n_in,
                              void* d_out, int out_size)
{
    const float* x     = (const float*)d_in[0];
    const float* W_in  = (const float*)d_in[1];
    const float* b_in  = (const float*)d_in[2];
    const float* W1    = (const float*)d_in[3];
    const float* W2    = (const float*)d_in[4];
    const float* W3    = (const float*)d_in[5];
    const float* W4    = (const float*)d_in[6];
    const float* W_out = (const float*)d_in[7];
    const float* b_out = (const float*)d_in[8];
    float* out = (float*)d_out;

    cudaFuncSetAttribute(blocks_kernel,
                         cudaFuncAttributeMaxDynamicSharedMemorySize, K2_SMEM_BYTES);

    split_kernel<<<(TOT_ELEMS + 255) / 256, 256>>>(W_in, W1, W2, W3, W4);
    blocks_kernel<<<256, 128, K2_SMEM_BYTES>>>(x, b_in, W_out, b_out, out);
}